// round 1
// baseline (speedup 1.0000x reference)
#include <cuda_runtime.h>
#include <cstdint>

// Problem constants (fixed by the reference)
#define NN 100000
#define NF 512
#define NH 128
#define NC 40

// Scratch (device globals; no allocation allowed)
__device__ float g_supp1[NN * NH];   // x @ W1            51.2 MB
__device__ float g_h[NN * NH];       // spmm1 accum + b1  51.2 MB
__device__ float g_supp2[NN * NC];   // x2 @ W2           16 MB
__device__ float g_x3[NN * NC];      // spmm2 accum + b2  16 MB

// ---------------------------------------------------------------------------
// GEMM1: supp1[N,128] = x[N,512] @ W1[512,128]
// BM=64, BN=128(full), BK=16, 256 threads, each computes 8x4 outputs.
// ---------------------------------------------------------------------------
__global__ __launch_bounds__(256) void gemm1_kernel(
    const float* __restrict__ x, const float* __restrict__ W1,
    float* __restrict__ out)
{
    __shared__ float As[64][16];
    __shared__ float Bs[16][128];

    const int block_row = blockIdx.x * 64;
    const int t  = threadIdx.x;
    const int tr = t >> 5;      // 0..7 row group (8 rows each)
    const int tc = t & 31;      // 0..31 col group (4 cols each)

    float acc[8][4];
#pragma unroll
    for (int r = 0; r < 8; r++)
#pragma unroll
        for (int j = 0; j < 4; j++) acc[r][j] = 0.0f;

    for (int k0 = 0; k0 < NF; k0 += 16) {
        // Load As: 64x16 = 256 float4
        {
            int r  = t >> 2;
            int kk = (t & 3) << 2;
            int gr = block_row + r;
            float4 v = make_float4(0.f, 0.f, 0.f, 0.f);
            if (gr < NN) v = *(const float4*)&x[(size_t)gr * NF + k0 + kk];
            *(float4*)&As[r][kk] = v;
        }
        // Load Bs: 16x128 = 512 float4, 2 per thread
#pragma unroll
        for (int j = 0; j < 2; j++) {
            int i  = t + j * 256;
            int kk = i >> 5;
            int c  = (i & 31) << 2;
            *(float4*)&Bs[kk][c] = *(const float4*)&W1[(size_t)(k0 + kk) * NH + c];
        }
        __syncthreads();

#pragma unroll
        for (int kk = 0; kk < 16; kk++) {
            float4 bv = *(const float4*)&Bs[kk][tc << 2];
#pragma unroll
            for (int r = 0; r < 8; r++) {
                float a = As[(tr << 3) + r][kk];
                acc[r][0] = fmaf(a, bv.x, acc[r][0]);
                acc[r][1] = fmaf(a, bv.y, acc[r][1]);
                acc[r][2] = fmaf(a, bv.z, acc[r][2]);
                acc[r][3] = fmaf(a, bv.w, acc[r][3]);
            }
        }
        __syncthreads();
    }

#pragma unroll
    for (int r = 0; r < 8; r++) {
        int gr = block_row + (tr << 3) + r;
        if (gr < NN)
            *(float4*)&out[(size_t)gr * NH + (tc << 2)] =
                make_float4(acc[r][0], acc[r][1], acc[r][2], acc[r][3]);
    }
}

// ---------------------------------------------------------------------------
// init h[i,f] = b1[f]   (12.8M elems)
// ---------------------------------------------------------------------------
__global__ void init_h_kernel(const float* __restrict__ b1, float* __restrict__ h)
{
    int idx = blockIdx.x * blockDim.x + threadIdx.x;
    if (idx < NN * NH) h[idx] = b1[idx & (NH - 1)];
}

// ---------------------------------------------------------------------------
// SpMM1: h[row] += w * supp1[col]  (128 floats/edge), warp-per-edge,
// 32 edges batched per warp iteration, vector red.global.add.v4.f32
// ---------------------------------------------------------------------------
__global__ __launch_bounds__(256) void spmm1_kernel(
    const int* __restrict__ er, const int* __restrict__ ec,
    const float* __restrict__ ew, const float* __restrict__ supp,
    float* __restrict__ h, int E)
{
    const int lane  = threadIdx.x & 31;
    const int warp  = (blockIdx.x * blockDim.x + threadIdx.x) >> 5;
    const int nwarp = (gridDim.x * blockDim.x) >> 5;
    const float4* suppv = (const float4*)supp;

    for (int base = warp * 32; base < E; base += nwarp * 32) {
        int e = base + lane;
        int r = 0, c = 0; float w = 0.0f;
        if (e < E) { r = er[e]; c = ec[e]; w = ew[e]; }
        int cnt = min(32, E - base);
        for (int j = 0; j < cnt; j++) {
            int   rj = __shfl_sync(0xffffffffu, r, j);
            int   cj = __shfl_sync(0xffffffffu, c, j);
            float wj = __shfl_sync(0xffffffffu, w, j);
            float4 g = suppv[(size_t)cj * (NH / 4) + lane];
            float* dst = &h[(size_t)rj * NH + (lane << 2)];
            asm volatile("red.global.add.v4.f32 [%0], {%1,%2,%3,%4};"
                         :: "l"(dst), "f"(g.x * wj), "f"(g.y * wj),
                            "f"(g.z * wj), "f"(g.w * wj) : "memory");
        }
    }
}

// ---------------------------------------------------------------------------
// x2 = relu(h) * drop_mask  -> written straight into d_out (second segment)
// ---------------------------------------------------------------------------
__global__ void relu_drop_kernel(const float* __restrict__ h,
                                 const float* __restrict__ mask,
                                 float* __restrict__ x2)
{
    int idx = blockIdx.x * blockDim.x + threadIdx.x;
    if (idx < NN * NH) x2[idx] = fmaxf(h[idx], 0.0f) * mask[idx];
}

// ---------------------------------------------------------------------------
// GEMM2: supp2[N,40] = x2[N,128] @ W2[128,40]. Warp-per-row, W2 in smem.
// Lanes cover classes lane and lane+32 (lane<8).
// ---------------------------------------------------------------------------
__global__ __launch_bounds__(256) void gemm2_kernel(
    const float* __restrict__ x2, const float* __restrict__ W2,
    float* __restrict__ out)
{
    __shared__ float sW2[NH * NC];  // 20 KB
    for (int i = threadIdx.x; i < NH * NC; i += blockDim.x) sW2[i] = W2[i];
    __syncthreads();

    const int lane = threadIdx.x & 31;
    const int wid  = threadIdx.x >> 5;
    const int row  = blockIdx.x * 8 + wid;
    if (row >= NN) return;

    float acc1 = 0.0f, acc2 = 0.0f;
    const float* xr = &x2[(size_t)row * NH];
#pragma unroll 8
    for (int k = 0; k < NH; k++) {
        float xv = xr[k];
        acc1 = fmaf(xv, sW2[k * NC + lane], acc1);
        if (lane < 8) acc2 = fmaf(xv, sW2[k * NC + 32 + lane], acc2);
    }
    out[(size_t)row * NC + lane] = acc1;
    if (lane < 8) out[(size_t)row * NC + 32 + lane] = acc2;
}

// ---------------------------------------------------------------------------
// init x3[i,c] = b2[c]
// ---------------------------------------------------------------------------
__global__ void init_x3_kernel(const float* __restrict__ b2, float* __restrict__ x3)
{
    int idx = blockIdx.x * blockDim.x + threadIdx.x;
    if (idx < NN * NC) x3[idx] = b2[idx % NC];
}

// ---------------------------------------------------------------------------
// SpMM2: x3[row] += w * supp2[col] (40 floats/edge = 10 float4, lanes 0..9)
// ---------------------------------------------------------------------------
__global__ __launch_bounds__(256) void spmm2_kernel(
    const int* __restrict__ er, const int* __restrict__ ec,
    const float* __restrict__ ew, const float* __restrict__ supp,
    float* __restrict__ x3, int E)
{
    const int lane  = threadIdx.x & 31;
    const int warp  = (blockIdx.x * blockDim.x + threadIdx.x) >> 5;
    const int nwarp = (gridDim.x * blockDim.x) >> 5;
    const float4* suppv = (const float4*)supp;

    for (int base = warp * 32; base < E; base += nwarp * 32) {
        int e = base + lane;
        int r = 0, c = 0; float w = 0.0f;
        if (e < E) { r = er[e]; c = ec[e]; w = ew[e]; }
        int cnt = min(32, E - base);
        for (int j = 0; j < cnt; j++) {
            int   rj = __shfl_sync(0xffffffffu, r, j);
            int   cj = __shfl_sync(0xffffffffu, c, j);
            float wj = __shfl_sync(0xffffffffu, w, j);
            if (lane < NC / 4) {
                float4 g = suppv[(size_t)cj * (NC / 4) + lane];
                float* dst = &x3[(size_t)rj * NC + (lane << 2)];
                asm volatile("red.global.add.v4.f32 [%0], {%1,%2,%3,%4};"
                             :: "l"(dst), "f"(g.x * wj), "f"(g.y * wj),
                                "f"(g.z * wj), "f"(g.w * wj) : "memory");
            }
        }
    }
}

// ---------------------------------------------------------------------------
// log_softmax over 40 classes; warp per row (lanes cover c=lane, c=lane+32)
// ---------------------------------------------------------------------------
__global__ __launch_bounds__(256) void lsm_kernel(const float* __restrict__ x3,
                                                  float* __restrict__ out)
{
    const int lane = threadIdx.x & 31;
    const int wid  = threadIdx.x >> 5;
    const int row  = blockIdx.x * 8 + wid;
    if (row >= NN) return;

    float v1 = x3[(size_t)row * NC + lane];
    float v2 = (lane < 8) ? x3[(size_t)row * NC + 32 + lane] : -3.4e38f;

    float m = fmaxf(v1, v2);
#pragma unroll
    for (int o = 16; o > 0; o >>= 1)
        m = fmaxf(m, __shfl_xor_sync(0xffffffffu, m, o));

    float s = __expf(v1 - m) + ((lane < 8) ? __expf(v2 - m) : 0.0f);
#pragma unroll
    for (int o = 16; o > 0; o >>= 1)
        s += __shfl_xor_sync(0xffffffffu, s, o);

    float lse = m + __logf(s);
    out[(size_t)row * NC + lane] = v1 - lse;
    if (lane < 8) out[(size_t)row * NC + 32 + lane] = v2 - lse;
}

// ---------------------------------------------------------------------------
extern "C" void kernel_launch(void* const* d_in, const int* in_sizes, int n_in,
                              void* d_out, int out_size)
{
    const float* x    = (const float*)d_in[0];
    const int*   er   = (const int*)  d_in[1];
    const int*   ec   = (const int*)  d_in[2];
    const float* ew   = (const float*)d_in[3];
    const float* W1   = (const float*)d_in[4];
    const float* b1   = (const float*)d_in[5];
    const float* W2   = (const float*)d_in[6];
    const float* b2   = (const float*)d_in[7];
    const float* mask = (const float*)d_in[8];
    const int E = in_sizes[1];

    float* out_lsm = (float*)d_out;                 // [N, 40]
    float* out_x2  = (float*)d_out + (size_t)NN * NC; // [N, 128]

    float *supp1, *h, *supp2, *x3;
    cudaGetSymbolAddress((void**)&supp1, g_supp1);
    cudaGetSymbolAddress((void**)&h,     g_h);
    cudaGetSymbolAddress((void**)&supp2, g_supp2);
    cudaGetSymbolAddress((void**)&x3,    g_x3);

    // Layer 1
    gemm1_kernel<<<(NN + 63) / 64, 256>>>(x, W1, supp1);
    init_h_kernel<<<(NN * NH + 255) / 256, 256>>>(b1, h);
    spmm1_kernel<<<2368, 256>>>(er, ec, ew, supp1, h, E);
    relu_drop_kernel<<<(NN * NH + 255) / 256, 256>>>(h, mask, out_x2);

    // Layer 2
    gemm2_kernel<<<(NN + 7) / 8, 256>>>(out_x2, W2, supp2);
    init_x3_kernel<<<(NN * NC + 255) / 256, 256>>>(b2, x3);
    spmm2_kernel<<<2368, 256>>>(er, ec, ew, supp2, x3, E);
    lsm_kernel<<<(NN + 7) / 8, 256>>>(x3, out_lsm);
}